// round 2
// baseline (speedup 1.0000x reference)
#include <cuda_runtime.h>
#include <math.h>

// ESN: B=64, T=256, I=128, R=2048, O=10, alpha=0.5
#define BB 64
#define TT 256
#define II 128
#define RR 2048
#define OO 10
#define NCTA 128
#define NTHR 256
#define JS 16   // reservoir columns owned per CTA
#define KT 256  // k-tile for res staging

// Double-buffered transposed reservoir state: resT[buf][r][b]
__device__ float g_resT[2][RR * BB];
__device__ unsigned g_cnt;
__device__ unsigned g_gen;

// ---------- f32x2 packed FMA (sm_103a FFMA2) ----------
static __device__ __forceinline__ unsigned long long dup2(float v) {
    unsigned long long r;
    unsigned u = __float_as_uint(v);
    asm("mov.b64 %0, {%1, %1};" : "=l"(r) : "r"(u));
    return r;
}
static __device__ __forceinline__ void fma2(unsigned long long& a,
                                            unsigned long long x,
                                            unsigned long long y) {
    asm("fma.rn.f32x2 %0, %1, %2, %0;" : "+l"(a) : "l"(x), "l"(y));
}
static __device__ __forceinline__ unsigned ld_acq(const unsigned* p) {
    unsigned v;
    asm volatile("ld.acquire.gpu.u32 %0, [%1];" : "=r"(v) : "l"(p));
    return v;
}

// Grid-wide barrier: monotonically increasing generation counter.
// Self-consistent across graph replays (no reset needed).
static __device__ __forceinline__ void grid_sync() {
    __syncthreads();
    if (threadIdx.x == 0) {
        __threadfence();
        unsigned g = ld_acq(&g_gen);
        unsigned v = atomicAdd(&g_cnt, 1);
        if (v == NCTA - 1) {
            g_cnt = 0;
            asm volatile("st.release.gpu.u32 [%0], %1;" ::"l"(&g_gen), "r"(g + 1)
                         : "memory");
        } else {
            while (ld_acq(&g_gen) == g) { __nanosleep(64); }
        }
    }
    __syncthreads();
}

// =====================================================================
// One persistent kernel: xin precompute + 256-step leaky-ESN scan +
// readout. 128 CTAs x 256 threads, 1 grid barrier per step.
// Dynamic smem: sH = h2h[:, j-slice] (2048x16 fp32, persistent) followed
// by sR = res k-tile (256x64 fp32) which phase A overlays with x-tile+i2h.
// =====================================================================
extern "C" __global__ void __launch_bounds__(NTHR, 1)
esn_scan(const float* __restrict__ x, const float* __restrict__ i2h,
         const float* __restrict__ h2h, const float* __restrict__ ow,
         const float* __restrict__ ob, float* __restrict__ out,
         float* __restrict__ hid) {
    extern __shared__ float sm[];
    float* sH = sm;            // RR*JS floats
    float* sR = sm + RR * JS;  // KT*BB floats
    const int tid = threadIdx.x;
    const int cta = blockIdx.x;
    const int j0 = cta * JS;

    // ---------------- Phase A: xin = x @ i2h (own j-slice, all (b,t)) ----
    {
        float* sX = sR;             // [64][132] padded x tile
        float* si = sR + 64 * 132;  // [128][16] i2h slice
        for (int i = tid; i < II * JS; i += NTHR) {
            int k = i >> 4, jj = i & 15;
            si[i] = i2h[k * RR + j0 + jj];
        }
        const int row = tid >> 2;  // 0..63
        const int jq = tid & 3;    // 0..3
        for (int rt = 0; rt < BB * TT; rt += 64) {
            __syncthreads();
            for (int i = tid; i < 64 * II / 4; i += NTHR) {  // 2048 float4
                int r = i >> 5, q = i & 31;
                *(float4*)&sX[r * 132 + q * 4] =
                    *(const float4*)&x[(rt + r) * II + q * 4];
            }
            __syncthreads();
            unsigned long long a0 = 0ull, a1 = 0ull;
#pragma unroll 8
            for (int k = 0; k < II; k++) {
                unsigned long long xv = dup2(sX[row * 132 + k]);
                double2 hv = *(const double2*)&si[k * 16 + jq * 4];
                fma2(a0, xv, __double_as_longlong(hv.x));
                fma2(a1, xv, __double_as_longlong(hv.y));
            }
            float4 o;
            o.x = __uint_as_float((unsigned)a0);
            o.y = __uint_as_float((unsigned)(a0 >> 32));
            o.z = __uint_as_float((unsigned)a1);
            o.w = __uint_as_float((unsigned)(a1 >> 32));
            *(float4*)&hid[(rt + row) * RR + j0 + jq * 4] = o;
        }
    }
    __syncthreads();

    // ---------------- Load persistent h2h slice into smem ----------------
    for (int i = tid; i < RR * JS; i += NTHR) {
        int k = i >> 4, jj = i & 15;
        sH[i] = h2h[k * RR + j0 + jj];
    }
    __syncthreads();

    // ---------------- Scan ----------------
    // Lane mapping for gemm+epilogue: warp w owns b in [8w, 8w+8),
    // lane l: b = 8w + (l&7), jg = l>>3 (4 j-columns each).
    const int w = tid >> 5, l = tid & 31;
    const int b = w * 8 + (l & 7);
    const int jg = l >> 3;
    float4 prev = make_float4(0.f, 0.f, 0.f, 0.f);

    for (int t = 0; t < TT; t++) {
        unsigned long long a0 = 0ull, a1 = 0ull;
        if (t > 0) {
            const float* rsrc = &g_resT[(t - 1) & 1][0];
            for (int kt = 0; kt < RR; kt += KT) {
                for (int i = tid; i < KT * BB / 4; i += NTHR) {  // 4096 float4
                    int kk = i >> 4, q = i & 15;
                    *(float4*)&sR[kk * 64 + q * 4] =
                        *(const float4*)&rsrc[(kt + kk) * 64 + q * 4];
                }
                __syncthreads();
#pragma unroll 8
                for (int kk = 0; kk < KT; kk++) {
                    unsigned long long av = dup2(sR[kk * 64 + b]);
                    double2 hv = *(const double2*)&sH[(kt + kk) * 16 + jg * 4];
                    fma2(a0, av, __double_as_longlong(hv.x));
                    fma2(a1, av, __double_as_longlong(hv.y));
                }
                __syncthreads();
            }
        }
        // epilogue: res_t = 0.5*prev + 0.5*tanh(xin_t + gemm)
        float4 s;
        s.x = __uint_as_float((unsigned)a0);
        s.y = __uint_as_float((unsigned)(a0 >> 32));
        s.z = __uint_as_float((unsigned)a1);
        s.w = __uint_as_float((unsigned)(a1 >> 32));
        float4 xv = *(const float4*)&hid[(b * TT + t) * RR + j0 + jg * 4];
        float4 nr;
        nr.x = 0.5f * prev.x + 0.5f * tanhf(s.x + xv.x);
        nr.y = 0.5f * prev.y + 0.5f * tanhf(s.y + xv.y);
        nr.z = 0.5f * prev.z + 0.5f * tanhf(s.z + xv.z);
        nr.w = 0.5f * prev.w + 0.5f * tanhf(s.w + xv.w);
        prev = nr;
        *(float4*)&hid[(b * TT + t) * RR + j0 + jg * 4] = nr;
        float* wdst = &g_resT[t & 1][0];
        const int jb = j0 + jg * 4;
        wdst[(jb + 0) * 64 + b] = nr.x;
        wdst[(jb + 1) * 64 + b] = nr.y;
        wdst[(jb + 2) * 64 + b] = nr.z;
        wdst[(jb + 3) * 64 + b] = nr.w;
        grid_sync();
    }

    // ---------------- Readout: out[b] = res_last[b] @ out_w + out_b ------
    if (cta < BB) {
        const float* res = &hid[(cta * TT + (TT - 1)) * RR];
        float acc[OO];
#pragma unroll
        for (int o = 0; o < OO; o++) acc[o] = 0.f;
        for (int r = tid; r < RR; r += NTHR) {
            float rv = res[r];
#pragma unroll
            for (int o = 0; o < OO; o++) acc[o] += rv * ow[r * OO + o];
        }
        float* red = sm;  // NTHR*OO floats, reuse smem
        __syncthreads();
#pragma unroll
        for (int o = 0; o < OO; o++) red[tid + o * NTHR] = acc[o];
        __syncthreads();
        for (int s2 = NTHR / 2; s2 > 0; s2 >>= 1) {
            if (tid < s2) {
#pragma unroll
                for (int o = 0; o < OO; o++)
                    red[tid + o * NTHR] += red[tid + s2 + o * NTHR];
            }
            __syncthreads();
        }
        if (tid < OO) out[cta * OO + tid] = red[tid * NTHR] + ob[tid];
    }
}

extern "C" void kernel_launch(void* const* d_in, const int* in_sizes, int n_in,
                              void* d_out, int out_size) {
    const float* x = (const float*)d_in[0];    // (64,256,128)
    const float* i2h = (const float*)d_in[1];  // (128,2048)
    const float* h2h = (const float*)d_in[2];  // (2048,2048)
    const float* ow = (const float*)d_in[3];   // (2048,10)
    const float* ob = (const float*)d_in[4];   // (10,)
    float* out = (float*)d_out;
    float* hid = out + BB * OO;

    const int smem_bytes = (RR * JS + KT * BB) * (int)sizeof(float);  // 192 KB
    cudaFuncSetAttribute(esn_scan, cudaFuncAttributeMaxDynamicSharedMemorySize,
                         smem_bytes);
    esn_scan<<<NCTA, NTHR, smem_bytes>>>(x, i2h, h2h, ow, ob, out, hid);
}

// round 3
// speedup vs baseline: 2.1621x; 2.1621x over previous
#include <cuda_runtime.h>
#include <math.h>

// ESN: B=64, T=256, I=128, R=2048, O=10, alpha=0.5
#define BB 64
#define TT 256
#define II 128
#define RR 2048
#define OO 10
#define NCTA 128
#define NTHR 256
#define JS 16   // reservoir columns per CTA
#define KT 256  // k-tile for res staging

// Double-buffered transposed reservoir state resT[buf][r][b]
__device__ float g_resT[2][RR * BB];
__device__ unsigned g_cnt, g_gen;

static __device__ __forceinline__ unsigned long long dup2(float v) {
    unsigned long long r;
    unsigned u = __float_as_uint(v);
    asm("mov.b64 %0, {%1, %1};" : "=l"(r) : "r"(u));
    return r;
}
static __device__ __forceinline__ void fma2(unsigned long long& a,
                                            unsigned long long x,
                                            unsigned long long y) {
    asm("fma.rn.f32x2 %0, %1, %2, %0;" : "+l"(a) : "l"(x), "l"(y));
}
static __device__ __forceinline__ float lo32(unsigned long long a) {
    return __uint_as_float((unsigned)a);
}
static __device__ __forceinline__ float hi32(unsigned long long a) {
    return __uint_as_float((unsigned)(a >> 32));
}
static __device__ __forceinline__ unsigned ld_acq(const unsigned* p) {
    unsigned v;
    asm volatile("ld.acquire.gpu.u32 %0, [%1];" : "=r"(v) : "l"(p));
    return v;
}

static __device__ __forceinline__ void grid_sync() {
    __syncthreads();
    if (threadIdx.x == 0) {
        __threadfence();
        unsigned g = ld_acq(&g_gen);
        unsigned v = atomicAdd(&g_cnt, 1);
        if (v == NCTA - 1) {
            g_cnt = 0;
            asm volatile("st.release.gpu.u32 [%0], %1;" ::"l"(&g_gen), "r"(g + 1)
                         : "memory");
        } else {
            while (ld_acq(&g_gen) == g) { __nanosleep(64); }
        }
    }
    __syncthreads();
}

// smem: sH = h2h slice [2048][16] (128KB, persistent)
//       sR = union{ res k-tile [256][64] (64KB), reduce buf 16*257 quads,
//                   phase-A x tile }  (65.8KB)
#define SMEM_FLOATS (RR * JS + 16 * 257 * 4 + 16)

extern "C" __global__ void __launch_bounds__(NTHR, 1)
esn_scan(const float* __restrict__ x, const float* __restrict__ i2h,
         const float* __restrict__ h2h, const float* __restrict__ ow,
         const float* __restrict__ ob, float* __restrict__ out,
         float* __restrict__ hid) {
    extern __shared__ float sm[];
    float* sH = sm;
    float* sR = sm + RR * JS;
    const int tid = threadIdx.x;
    const int cta = blockIdx.x;
    const int j0 = cta * JS;

    // ---------------- Phase A: xin = x @ i2h for own j-slice ----------------
    {
        float* sX = sR;             // [64][132] padded x tile
        float* si = sR + 64 * 132;  // [128][16] i2h slice
        for (int i = tid; i < II * JS; i += NTHR) {
            int k = i >> 4, jj = i & 15;
            si[i] = i2h[k * RR + j0 + jj];
        }
        const int row = tid >> 2;
        const int jq = tid & 3;
        for (int rt = 0; rt < BB * TT; rt += 64) {
            __syncthreads();
            for (int i = tid; i < 64 * II / 4; i += NTHR) {
                int r = i >> 5, q = i & 31;
                *(float4*)&sX[r * 132 + q * 4] =
                    *(const float4*)&x[(rt + r) * II + q * 4];
            }
            __syncthreads();
            unsigned long long a0 = 0ull, a1 = 0ull;
#pragma unroll 8
            for (int k = 0; k < II; k++) {
                unsigned long long xv = dup2(sX[row * 132 + k]);
                ulonglong2 hv = *(const ulonglong2*)&si[k * 16 + jq * 4];
                fma2(a0, xv, hv.x);
                fma2(a1, xv, hv.y);
            }
            float4 o = make_float4(lo32(a0), hi32(a0), lo32(a1), hi32(a1));
            *(float4*)&hid[(rt + row) * RR + j0 + jq * 4] = o;
        }
        __syncthreads();
    }

    // ---------------- Persistent h2h slice -> smem ----------------
    for (int i = tid; i < RR * JS; i += NTHR) {
        int k = i >> 4, jj = i & 15;
        sH[i] = h2h[k * RR + j0 + jj];
    }

    // ---------------- Scan ----------------
    // GEMM mapping: tile = tid&15 -> (b0 = (tile>>1)*8, jl = (tile&1)*8),
    // ks = tid>>4 handles k === ks (mod 16).
    const int tile = tid & 15;
    const int ks = tid >> 4;
    const int b0 = (tile >> 1) * 8;
    const int jl = (tile & 1) * 8;
    // Reduction/epilogue mapping: (tr = tid&15, ir = tid>>4) -> one float4
    const int tr = tid & 15;
    const int ir = tid >> 4;
    const int eb = (tr >> 1) * 8 + (ir >> 1);
    const int ej = j0 + (tr & 1) * 8 + (ir & 1) * 4;
    float4 prev = make_float4(0.f, 0.f, 0.f, 0.f);
    float4* sQ = (float4*)sR;

    for (int t = 0; t < TT; t++) {
        float4 q = make_float4(0.f, 0.f, 0.f, 0.f);
        if (t > 0) {
            unsigned long long acc[32];
#pragma unroll
            for (int i = 0; i < 32; i++) acc[i] = 0ull;
            const float* rsrc = &g_resT[(t - 1) & 1][0];
            for (int kt = 0; kt < RR; kt += KT) {
                // stage res tile [KT][64]
                for (int i = tid; i < KT * BB / 4; i += NTHR) {
                    int r = i >> 4, c = i & 15;
                    *(float4*)&sR[r * 64 + c * 4] =
                        *(const float4*)&rsrc[(kt + r) * 64 + c * 4];
                }
                __syncthreads();
#pragma unroll
                for (int kk = 0; kk < KT / 16; kk++) {
                    const int lr = kk * 16 + ks;
                    float4 r0 = *(const float4*)&sR[lr * 64 + b0];
                    float4 r1 = *(const float4*)&sR[lr * 64 + b0 + 4];
                    ulonglong2 hA = *(const ulonglong2*)&sH[(kt + lr) * 16 + jl];
                    ulonglong2 hB =
                        *(const ulonglong2*)&sH[(kt + lr) * 16 + jl + 4];
                    unsigned long long d;
                    d = dup2(r0.x);
                    fma2(acc[0], d, hA.x);  fma2(acc[1], d, hA.y);
                    fma2(acc[2], d, hB.x);  fma2(acc[3], d, hB.y);
                    d = dup2(r0.y);
                    fma2(acc[4], d, hA.x);  fma2(acc[5], d, hA.y);
                    fma2(acc[6], d, hB.x);  fma2(acc[7], d, hB.y);
                    d = dup2(r0.z);
                    fma2(acc[8], d, hA.x);  fma2(acc[9], d, hA.y);
                    fma2(acc[10], d, hB.x); fma2(acc[11], d, hB.y);
                    d = dup2(r0.w);
                    fma2(acc[12], d, hA.x); fma2(acc[13], d, hA.y);
                    fma2(acc[14], d, hB.x); fma2(acc[15], d, hB.y);
                    d = dup2(r1.x);
                    fma2(acc[16], d, hA.x); fma2(acc[17], d, hA.y);
                    fma2(acc[18], d, hB.x); fma2(acc[19], d, hB.y);
                    d = dup2(r1.y);
                    fma2(acc[20], d, hA.x); fma2(acc[21], d, hA.y);
                    fma2(acc[22], d, hB.x); fma2(acc[23], d, hB.y);
                    d = dup2(r1.z);
                    fma2(acc[24], d, hA.x); fma2(acc[25], d, hA.y);
                    fma2(acc[26], d, hB.x); fma2(acc[27], d, hB.y);
                    d = dup2(r1.w);
                    fma2(acc[28], d, hA.x); fma2(acc[29], d, hA.y);
                    fma2(acc[30], d, hB.x); fma2(acc[31], d, hB.y);
                }
                __syncthreads();
            }
            // write 16 partial quads (conflict-free: lane stride 16B)
#pragma unroll
            for (int i = 0; i < 16; i++) {
                int bq = i >> 1, jh = i & 1;
                unsigned long long a0 = acc[bq * 4 + jh * 2];
                unsigned long long a1 = acc[bq * 4 + jh * 2 + 1];
                sQ[i * 257 + tid] =
                    make_float4(lo32(a0), hi32(a0), lo32(a1), hi32(a1));
            }
            __syncthreads();
            // 16-way reduce for quad (tr, ir)
#pragma unroll
            for (int s2 = 0; s2 < 16; s2++) {
                float4 p = sQ[ir * 257 + s2 * 16 + tr];
                q.x += p.x; q.y += p.y; q.z += p.z; q.w += p.w;
            }
        }
        // epilogue: res_t = 0.5*prev + 0.5*tanh(xin + gemm)
        float4 xv = *(const float4*)&hid[(eb * TT + t) * RR + ej];
        float4 nr;
        nr.x = 0.5f * prev.x + 0.5f * tanhf(q.x + xv.x);
        nr.y = 0.5f * prev.y + 0.5f * tanhf(q.y + xv.y);
        nr.z = 0.5f * prev.z + 0.5f * tanhf(q.z + xv.z);
        nr.w = 0.5f * prev.w + 0.5f * tanhf(q.w + xv.w);
        prev = nr;
        *(float4*)&hid[(eb * TT + t) * RR + ej] = nr;
        float* wd = &g_resT[t & 1][0];
        wd[(ej + 0) * BB + eb] = nr.x;
        wd[(ej + 1) * BB + eb] = nr.y;
        wd[(ej + 2) * BB + eb] = nr.z;
        wd[(ej + 3) * BB + eb] = nr.w;
        grid_sync();
    }

    // ---------------- Readout ----------------
    if (cta < BB) {
        const float* res = &hid[(cta * TT + (TT - 1)) * RR];
        float acc[OO];
#pragma unroll
        for (int o = 0; o < OO; o++) acc[o] = 0.f;
        for (int r = tid; r < RR; r += NTHR) {
            float rv = res[r];
#pragma unroll
            for (int o = 0; o < OO; o++) acc[o] += rv * ow[r * OO + o];
        }
        float* red = sm;
        __syncthreads();
#pragma unroll
        for (int o = 0; o < OO; o++) red[tid + o * NTHR] = acc[o];
        __syncthreads();
        for (int s2 = NTHR / 2; s2 > 0; s2 >>= 1) {
            if (tid < s2) {
#pragma unroll
                for (int o = 0; o < OO; o++)
                    red[tid + o * NTHR] += red[tid + s2 + o * NTHR];
            }
            __syncthreads();
        }
        if (tid < OO) out[cta * OO + tid] = red[tid * NTHR] + ob[tid];
    }
}

extern "C" void kernel_launch(void* const* d_in, const int* in_sizes, int n_in,
                              void* d_out, int out_size) {
    const float* x = (const float*)d_in[0];
    const float* i2h = (const float*)d_in[1];
    const float* h2h = (const float*)d_in[2];
    const float* ow = (const float*)d_in[3];
    const float* ob = (const float*)d_in[4];
    float* out = (float*)d_out;
    float* hid = out + BB * OO;

    const int smem_bytes = SMEM_FLOATS * (int)sizeof(float);  // ~197 KB
    cudaFuncSetAttribute(esn_scan, cudaFuncAttributeMaxDynamicSharedMemorySize,
                         smem_bytes);
    esn_scan<<<NCTA, NTHR, smem_bytes>>>(x, i2h, h2h, ow, ob, out, hid);
}

// round 6
// speedup vs baseline: 4.5625x; 2.1102x over previous
#include <cuda_runtime.h>
#include <cuda_bf16.h>
#include <stdint.h>
#include <math.h>

// ESN: B=64, T=256, I=128, R=2048, O=10, alpha=0.5
#define BB 64
#define TT 256
#define II 128
#define RR 2048
#define OO 10
#define NCTA 128
#define NTHR 256

// ---------------- device globals ----------------
__device__ __align__(256) __nv_bfloat16 g_AhiT[RR * RR];  // h2h^T hi
__device__ __align__(256) __nv_bfloat16 g_AloT[RR * RR];  // h2h^T lo
__device__ __align__(256) __nv_bfloat16 g_reshi[BB * RR];
__device__ __align__(256) __nv_bfloat16 g_reslo[BB * RR];
__device__ __align__(256) float g_part[8 * 16 * BB * 128];  // [ks][mt][b][jr]
__device__ unsigned g_cnt, g_gen;

// ---------------- smem layout (bytes) ----------------
// 528-byte row stride (512 data + 16 pad) -> conflict-free frag LDS
#define ROWB 528
#define SM_A_HI 0
#define SM_A_LO (128 * ROWB)            // 67584
#define SM_R_HI (2 * 128 * ROWB)        // 135168
#define SM_R_LO (SM_R_HI + 64 * ROWB)   // 168960
#define SM_TOTAL (SM_R_LO + 64 * ROWB)  // 202752

// ---------------- helpers ----------------
static __device__ __forceinline__ unsigned long long dup2(float v) {
    unsigned long long r;
    unsigned u = __float_as_uint(v);
    asm("mov.b64 %0, {%1, %1};" : "=l"(r) : "r"(u));
    return r;
}
static __device__ __forceinline__ void fma2(unsigned long long& a,
                                            unsigned long long x,
                                            unsigned long long y) {
    asm("fma.rn.f32x2 %0, %1, %2, %0;" : "+l"(a) : "l"(x), "l"(y));
}
static __device__ __forceinline__ float lo32(unsigned long long a) {
    return __uint_as_float((unsigned)a);
}
static __device__ __forceinline__ float hi32(unsigned long long a) {
    return __uint_as_float((unsigned)(a >> 32));
}
static __device__ __forceinline__ void mma_bf16(float* d, const unsigned* a,
                                                const unsigned* b) {
    asm volatile(
        "mma.sync.aligned.m16n8k16.row.col.f32.bf16.bf16.f32 "
        "{%0,%1,%2,%3}, {%4,%5,%6,%7}, {%8,%9}, {%0,%1,%2,%3};"
        : "+f"(d[0]), "+f"(d[1]), "+f"(d[2]), "+f"(d[3])
        : "r"(a[0]), "r"(a[1]), "r"(a[2]), "r"(a[3]), "r"(b[0]), "r"(b[1]));
}
static __device__ __forceinline__ unsigned ld_acq(const unsigned* p) {
    unsigned v;
    asm volatile("ld.acquire.gpu.u32 %0, [%1];" : "=r"(v) : "l"(p));
    return v;
}
static __device__ __forceinline__ void grid_sync() {
    __syncthreads();
    if (threadIdx.x == 0) {
        __threadfence();
        unsigned g = ld_acq(&g_gen);
        unsigned v = atomicAdd(&g_cnt, 1);
        if (v == NCTA - 1) {
            g_cnt = 0;
            asm volatile("st.release.gpu.u32 [%0], %1;" ::"l"(&g_gen),
                         "r"(g + 1)
                         : "memory");
        } else {
            while (ld_acq(&g_gen) == g) { __nanosleep(32); }
        }
    }
    __syncthreads();
}
static __device__ __forceinline__ unsigned pk(float a, float b) {
    __nv_bfloat162 h = __floats2bfloat162_rn(a, b);
    return *(unsigned*)&h;
}

extern "C" __global__ void __launch_bounds__(NTHR, 1)
esn_mma(const float* __restrict__ x, const float* __restrict__ i2h,
        const float* __restrict__ h2h, const float* __restrict__ ow,
        const float* __restrict__ ob, float* __restrict__ out,
        float* __restrict__ hid) {
    extern __shared__ char sm8[];
    const int tid = threadIdx.x;
    const int cta = blockIdx.x;

    // =========== Phase 0: h2h^T hi/lo split (2 x 128x128 tiles/CTA) =======
    {
        float* sT = (float*)sm8;  // 128 x 133 fp32 (68KB)
        for (int rep = 0; rep < 2; rep++) {
            int tt = cta * 2 + rep;
            int ti = tt >> 4, tj = tt & 15;
            __syncthreads();
            for (int idx = tid; idx < 16384; idx += NTHR) {
                int r = idx >> 7, c = idx & 127;
                sT[r * 133 + c] = h2h[(ti * 128 + r) * RR + tj * 128 + c];
            }
            __syncthreads();
            for (int idx = tid; idx < 16384; idx += NTHR) {
                int jl = idx >> 7, kl = idx & 127;
                float v = sT[kl * 133 + jl];  // transpose read, conflict-free
                __nv_bfloat16 bhi = __float2bfloat16_rn(v);
                __nv_bfloat16 blo =
                    __float2bfloat16_rn(v - __bfloat162float(bhi));
                int jg = tj * 128 + jl, kg = ti * 128 + kl;
                g_AhiT[jg * RR + kg] = bhi;
                g_AloT[jg * RR + kg] = blo;
            }
        }
        __syncthreads();
    }

    // =========== Phase A: xin = x @ i2h (SIMT FFMA2, own 16-col slice) ====
    {
        float* sX = (float*)sm8;             // [64][132]
        float* si = (float*)sm8 + 64 * 132;  // [128][16]
        const int j0c = cta * 16;
        for (int i = tid; i < II * 16; i += NTHR) {
            int k = i >> 4, jj = i & 15;
            si[i] = i2h[k * RR + j0c + jj];
        }
        const int row = tid >> 2;
        const int jq = tid & 3;
        for (int rt = 0; rt < BB * TT; rt += 64) {
            __syncthreads();
            for (int i = tid; i < 64 * II / 4; i += NTHR) {
                int r = i >> 5, q = i & 31;
                *(float4*)&sX[r * 132 + q * 4] =
                    *(const float4*)&x[(rt + r) * II + q * 4];
            }
            __syncthreads();
            unsigned long long a0 = 0ull, a1 = 0ull;
#pragma unroll 8
            for (int k = 0; k < II; k++) {
                unsigned long long xv = dup2(sX[row * 132 + k]);
                ulonglong2 hv = *(const ulonglong2*)&si[k * 16 + jq * 4];
                fma2(a0, xv, hv.x);
                fma2(a1, xv, hv.y);
            }
            float4 o = make_float4(lo32(a0), hi32(a0), lo32(a1), hi32(a1));
            *(float4*)&hid[(rt + row) * RR + j0c + jq * 4] = o;
        }
        __syncthreads();
    }
    grid_sync();

    // =========== Stage persistent h2h^T slice into smem ====================
    const int mt = cta & 15;  // j block of 128
    const int ks = cta >> 4;  // k block of 256
    for (int idx = tid; idx < 4096; idx += NTHR) {  // 4096 x 16B per buffer
        int row = idx >> 5, kc = idx & 31;
        *(uint4*)(sm8 + SM_A_HI + row * ROWB + kc * 16) =
            *(const uint4*)&g_AhiT[(mt * 128 + row) * RR + ks * 256 + kc * 8];
        *(uint4*)(sm8 + SM_A_LO + row * ROWB + kc * 16) =
            *(const uint4*)&g_AloT[(mt * 128 + row) * RR + ks * 256 + kc * 8];
    }
    __syncthreads();

    // =========== Scan ===========
    const int w = tid >> 5;       // warp 0..7 (warps 0-3 do mma)
    const int l = tid & 31;
    const int g = l >> 2, tg = l & 3;
    // epilogue mapping: one float4 per thread over B*R
    const int gt = cta * NTHR + tid;  // 0..32767
    const int b_e = gt >> 9;          // 0..63
    const int j0 = (gt & 511) * 4;    // 0..2044
    const int mt_e = j0 >> 7, jr0 = j0 & 127;
    float4 p0 = make_float4(0.f, 0.f, 0.f, 0.f);

    const char* sAhi = sm8 + SM_A_HI;
    const char* sAlo = sm8 + SM_A_LO;
    const char* sRhi = sm8 + SM_R_HI;
    const char* sRlo = sm8 + SM_R_LO;

    for (int t = 0; t < TT; t++) {
        if (t > 0) {
            // stage res tile [64][256] hi/lo
            for (int idx = tid; idx < 2048; idx += NTHR) {
                int row = idx >> 5, kc = idx & 31;
                *(uint4*)(sm8 + SM_R_HI + row * ROWB + kc * 16) =
                    *(const uint4*)&g_reshi[row * RR + ks * 256 + kc * 8];
                *(uint4*)(sm8 + SM_R_LO + row * ROWB + kc * 16) =
                    *(const uint4*)&g_reslo[row * RR + ks * 256 + kc * 8];
            }
            __syncthreads();
            if (w < 4) {
                float acc[2][8][4];
#pragma unroll
                for (int m = 0; m < 2; m++)
#pragma unroll
                    for (int n = 0; n < 8; n++)
#pragma unroll
                        for (int q = 0; q < 4; q++) acc[m][n][q] = 0.f;
                const int r0 = (32 * w + g) * ROWB;
                const int r1 = r0 + 16 * ROWB;
#pragma unroll 2
                for (int k16 = 0; k16 < 16; k16++) {
                    const int kb = k16 * 32 + 4 * tg;
                    unsigned ah0[4], ah1[4], al0[4], al1[4];
                    ah0[0] = *(const unsigned*)(sAhi + r0 + kb);
                    ah0[1] = *(const unsigned*)(sAhi + r0 + 8 * ROWB + kb);
                    ah0[2] = *(const unsigned*)(sAhi + r0 + kb + 16);
                    ah0[3] = *(const unsigned*)(sAhi + r0 + 8 * ROWB + kb + 16);
                    ah1[0] = *(const unsigned*)(sAhi + r1 + kb);
                    ah1[1] = *(const unsigned*)(sAhi + r1 + 8 * ROWB + kb);
                    ah1[2] = *(const unsigned*)(sAhi + r1 + kb + 16);
                    ah1[3] = *(const unsigned*)(sAhi + r1 + 8 * ROWB + kb + 16);
                    al0[0] = *(const unsigned*)(sAlo + r0 + kb);
                    al0[1] = *(const unsigned*)(sAlo + r0 + 8 * ROWB + kb);
                    al0[2] = *(const unsigned*)(sAlo + r0 + kb + 16);
                    al0[3] = *(const unsigned*)(sAlo + r0 + 8 * ROWB + kb + 16);
                    al1[0] = *(const unsigned*)(sAlo + r1 + kb);
                    al1[1] = *(const unsigned*)(sAlo + r1 + 8 * ROWB + kb);
                    al1[2] = *(const unsigned*)(sAlo + r1 + kb + 16);
                    al1[3] = *(const unsigned*)(sAlo + r1 + 8 * ROWB + kb + 16);
#pragma unroll
                    for (int nt = 0; nt < 8; nt++) {
                        const int rb = (nt * 8 + g) * ROWB;
                        unsigned bh[2], bl[2];
                        bh[0] = *(const unsigned*)(sRhi + rb + kb);
                        bh[1] = *(const unsigned*)(sRhi + rb + kb + 16);
                        bl[0] = *(const unsigned*)(sRlo + rb + kb);
                        bl[1] = *(const unsigned*)(sRlo + rb + kb + 16);
                        mma_bf16(acc[0][nt], ah0, bh);
                        mma_bf16(acc[0][nt], ah0, bl);
                        mma_bf16(acc[0][nt], al0, bh);
                        mma_bf16(acc[1][nt], ah1, bh);
                        mma_bf16(acc[1][nt], ah1, bl);
                        mma_bf16(acc[1][nt], al1, bh);
                    }
                }
                // store partials: g_part[((ks*16+mt)*64 + b)*128 + jr]
                const int pbase = (ks * 16 + mt) * 64;
#pragma unroll
                for (int m = 0; m < 2; m++) {
                    const int jr = 32 * w + m * 16 + g;
#pragma unroll
                    for (int nt = 0; nt < 8; nt++) {
                        const int bb2 = nt * 8 + 2 * tg;
                        g_part[(pbase + bb2) * 128 + jr] = acc[m][nt][0];
                        g_part[(pbase + bb2 + 1) * 128 + jr] = acc[m][nt][1];
                        g_part[(pbase + bb2) * 128 + jr + 8] = acc[m][nt][2];
                        g_part[(pbase + bb2 + 1) * 128 + jr + 8] =
                            acc[m][nt][3];
                    }
                }
            }
            grid_sync();
        }
        // ---- epilogue: one float4 (b_e, j0..j0+3) ----
        float4 q = make_float4(0.f, 0.f, 0.f, 0.f);
        if (t > 0) {
#pragma unroll
            for (int s = 0; s < 8; s++) {
                float4 pa = *(const float4*)
                    &g_part[((s * 16 + mt_e) * 64 + b_e) * 128 + jr0];
                q.x += pa.x; q.y += pa.y; q.z += pa.z; q.w += pa.w;
            }
        }
        float4 xv = *(const float4*)&hid[(b_e * TT + t) * RR + j0];
        float4 nr;
        nr.x = 0.5f * p0.x + 0.5f * tanhf(q.x + xv.x);
        nr.y = 0.5f * p0.y + 0.5f * tanhf(q.y + xv.y);
        nr.z = 0.5f * p0.z + 0.5f * tanhf(q.z + xv.z);
        nr.w = 0.5f * p0.w + 0.5f * tanhf(q.w + xv.w);
        p0 = nr;
        *(float4*)&hid[(b_e * TT + t) * RR + j0] = nr;
        float h0 = __bfloat162float(__float2bfloat16_rn(nr.x));
        float h1 = __bfloat162float(__float2bfloat16_rn(nr.y));
        float h2 = __bfloat162float(__float2bfloat16_rn(nr.z));
        float h3 = __bfloat162float(__float2bfloat16_rn(nr.w));
        uint2 uh, ul;
        uh.x = pk(h0, h1);
        uh.y = pk(h2, h3);
        ul.x = pk(nr.x - h0, nr.y - h1);
        ul.y = pk(nr.z - h2, nr.w - h3);
        *(uint2*)&g_reshi[b_e * RR + j0] = uh;
        *(uint2*)&g_reslo[b_e * RR + j0] = ul;
        grid_sync();
    }

    // =========== Readout ===========
    if (cta < BB) {
        const float* res = &hid[(cta * TT + (TT - 1)) * RR];
        float acc[OO];
#pragma unroll
        for (int o = 0; o < OO; o++) acc[o] = 0.f;
        for (int r = tid; r < RR; r += NTHR) {
            float rv = res[r];
#pragma unroll
            for (int o = 0; o < OO; o++) acc[o] += rv * ow[r * OO + o];
        }
        float* red = (float*)sm8;
        __syncthreads();
#pragma unroll
        for (int o = 0; o < OO; o++) red[o * NTHR + tid] = acc[o];
        __syncthreads();
        for (int s2 = NTHR / 2; s2 > 0; s2 >>= 1) {
            if (tid < s2) {
#pragma unroll
                for (int o = 0; o < OO; o++)
                    red[o * NTHR + tid] += red[o * NTHR + tid + s2];
            }
            __syncthreads();
        }
        if (tid < OO) out[cta * OO + tid] = red[tid * NTHR] + ob[tid];
    }
}

extern "C" void kernel_launch(void* const* d_in, const int* in_sizes, int n_in,
                              void* d_out, int out_size) {
    const float* x = (const float*)d_in[0];
    const float* i2h = (const float*)d_in[1];
    const float* h2h = (const float*)d_in[2];
    const float* ow = (const float*)d_in[3];
    const float* ob = (const float*)d_in[4];
    float* out = (float*)d_out;
    float* hid = out + BB * OO;

    cudaFuncSetAttribute(esn_mma, cudaFuncAttributeMaxDynamicSharedMemorySize,
                         SM_TOTAL);
    esn_mma<<<NCTA, NTHR, SM_TOTAL>>>(x, i2h, h2h, ow, ob, out, hid);
}

// round 7
// speedup vs baseline: 4.5663x; 1.0008x over previous
#include <cuda_runtime.h>
#include <cuda_bf16.h>
#include <stdint.h>
#include <math.h>

// ESN: B=64, T=256, I=128, R=2048, O=10, alpha=0.5
#define BB 64
#define TT 256
#define II 128
#define RR 2048
#define OO 10
#define NCTA 128
#define NTHR 256

// ---------------- device globals ----------------
__device__ __align__(256) __nv_bfloat16 g_AhiT[RR * RR];  // h2h^T hi
__device__ __align__(256) __nv_bfloat16 g_AloT[RR * RR];  // h2h^T lo
__device__ __align__(256) __nv_bfloat16 g_reshi[BB * RR];
__device__ __align__(256) __nv_bfloat16 g_reslo[BB * RR];
__device__ __align__(256) float g_part[8 * 16 * BB * 128];  // [ks][mt][b][jr]
__device__ unsigned g_cnt, g_gen;

// ---------------- smem layout (bytes) ----------------
// 528-byte row stride (512 data + 16 pad) -> conflict-free frag LDS
#define ROWB 528
#define SM_A_HI 0
#define SM_A_LO (128 * ROWB)            // 67584
#define SM_R_HI (2 * 128 * ROWB)        // 135168  (also reused as sP)
#define SM_R_LO (SM_R_HI + 64 * ROWB)   // 168960
#define SM_TOTAL (SM_R_LO + 64 * ROWB)  // 202752

// ---------------- helpers ----------------
static __device__ __forceinline__ unsigned long long dup2(float v) {
    unsigned long long r;
    unsigned u = __float_as_uint(v);
    asm("mov.b64 %0, {%1, %1};" : "=l"(r) : "r"(u));
    return r;
}
static __device__ __forceinline__ void fma2(unsigned long long& a,
                                            unsigned long long x,
                                            unsigned long long y) {
    asm("fma.rn.f32x2 %0, %1, %2, %0;" : "+l"(a) : "l"(x), "l"(y));
}
static __device__ __forceinline__ float lo32(unsigned long long a) {
    return __uint_as_float((unsigned)a);
}
static __device__ __forceinline__ float hi32(unsigned long long a) {
    return __uint_as_float((unsigned)(a >> 32));
}
static __device__ __forceinline__ void mma_bf16(float* d, const unsigned* a,
                                                const unsigned* b) {
    asm volatile(
        "mma.sync.aligned.m16n8k16.row.col.f32.bf16.bf16.f32 "
        "{%0,%1,%2,%3}, {%4,%5,%6,%7}, {%8,%9}, {%0,%1,%2,%3};"
        : "+f"(d[0]), "+f"(d[1]), "+f"(d[2]), "+f"(d[3])
        : "r"(a[0]), "r"(a[1]), "r"(a[2]), "r"(a[3]), "r"(b[0]), "r"(b[1]));
}
static __device__ __forceinline__ unsigned ld_acq(const unsigned* p) {
    unsigned v;
    asm volatile("ld.acquire.gpu.u32 %0, [%1];" : "=r"(v) : "l"(p));
    return v;
}
static __device__ __forceinline__ void grid_sync() {
    __syncthreads();
    if (threadIdx.x == 0) {
        __threadfence();
        unsigned g = ld_acq(&g_gen);
        unsigned v = atomicAdd(&g_cnt, 1);
        if (v == NCTA - 1) {
            g_cnt = 0;
            asm volatile("st.release.gpu.u32 [%0], %1;" ::"l"(&g_gen),
                         "r"(g + 1)
                         : "memory");
        } else {
            while (ld_acq(&g_gen) == g) { __nanosleep(32); }
        }
    }
    __syncthreads();
}
static __device__ __forceinline__ unsigned pk(float a, float b) {
    __nv_bfloat162 h = __floats2bfloat162_rn(a, b);
    return *(unsigned*)&h;
}

extern "C" __global__ void __launch_bounds__(NTHR, 1)
esn_mma(const float* __restrict__ x, const float* __restrict__ i2h,
        const float* __restrict__ h2h, const float* __restrict__ ow,
        const float* __restrict__ ob, float* __restrict__ out,
        float* __restrict__ hid) {
    extern __shared__ char sm8[];
    const int tid = threadIdx.x;
    const int cta = blockIdx.x;

    // =========== Phase 0: h2h^T hi/lo split (2 x 128x128 tiles/CTA) =======
    {
        float* sT = (float*)sm8;  // 128 x 133 fp32 (68KB)
        for (int rep = 0; rep < 2; rep++) {
            int tt = cta * 2 + rep;
            int ti = tt >> 4, tj = tt & 15;
            __syncthreads();
            for (int idx = tid; idx < 16384; idx += NTHR) {
                int r = idx >> 7, c = idx & 127;
                sT[r * 133 + c] = h2h[(ti * 128 + r) * RR + tj * 128 + c];
            }
            __syncthreads();
            for (int idx = tid; idx < 16384; idx += NTHR) {
                int jl = idx >> 7, kl = idx & 127;
                float v = sT[kl * 133 + jl];  // transpose read
                __nv_bfloat16 bhi = __float2bfloat16_rn(v);
                __nv_bfloat16 blo =
                    __float2bfloat16_rn(v - __bfloat162float(bhi));
                int jg = tj * 128 + jl, kg = ti * 128 + kl;
                g_AhiT[jg * RR + kg] = bhi;
                g_AloT[jg * RR + kg] = blo;
            }
        }
        __syncthreads();
    }

    // =========== Phase A: xin = x @ i2h (SIMT FFMA2, own 16-col slice) ====
    {
        float* sX = (float*)sm8;             // [64][132]
        float* si = (float*)sm8 + 64 * 132;  // [128][16]
        const int j0c = cta * 16;
        for (int i = tid; i < II * 16; i += NTHR) {
            int k = i >> 4, jj = i & 15;
            si[i] = i2h[k * RR + j0c + jj];
        }
        const int row = tid >> 2;
        const int jq = tid & 3;
        for (int rt = 0; rt < BB * TT; rt += 64) {
            __syncthreads();
            for (int i = tid; i < 64 * II / 4; i += NTHR) {
                int r = i >> 5, q = i & 31;
                *(float4*)&sX[r * 132 + q * 4] =
                    *(const float4*)&x[(rt + r) * II + q * 4];
            }
            __syncthreads();
            unsigned long long a0 = 0ull, a1 = 0ull;
#pragma unroll 8
            for (int k = 0; k < II; k++) {
                unsigned long long xv = dup2(sX[row * 132 + k]);
                ulonglong2 hv = *(const ulonglong2*)&si[k * 16 + jq * 4];
                fma2(a0, xv, hv.x);
                fma2(a1, xv, hv.y);
            }
            float4 o = make_float4(lo32(a0), hi32(a0), lo32(a1), hi32(a1));
            *(float4*)&hid[(rt + row) * RR + j0c + jq * 4] = o;
        }
        __syncthreads();
    }
    grid_sync();

    // =========== Stage persistent h2h^T slice into smem ====================
    const int mt = cta & 15;  // j block of 128
    const int ks = cta >> 4;  // k block of 256
    for (int idx = tid; idx < 4096; idx += NTHR) {
        int row = idx >> 5, kc = idx & 31;
        *(uint4*)(sm8 + SM_A_HI + row * ROWB + kc * 16) =
            *(const uint4*)&g_AhiT[(mt * 128 + row) * RR + ks * 256 + kc * 8];
        *(uint4*)(sm8 + SM_A_LO + row * ROWB + kc * 16) =
            *(const uint4*)&g_AloT[(mt * 128 + row) * RR + ks * 256 + kc * 8];
    }
    __syncthreads();

    // =========== Scan ===========
    const int w = tid >> 5;  // all 8 warps do mma
    const int l = tid & 31;
    const int g = l >> 2, tg = l & 3;
    const int mw = w & 3;   // m-pair: m-tiles 2mw, 2mw+1 (rows 32mw..32mw+31)
    const int nh = w >> 2;  // n-half: n-tiles 4nh..4nh+3
    // epilogue mapping: one float4 per thread over B*R
    const int gt = cta * NTHR + tid;  // 0..32767
    const int b_e = gt >> 9;          // 0..63
    const int j0 = (gt & 511) * 4;    // 0..2044
    const int mt_e = j0 >> 7, jr0 = j0 & 127;
    float4 p0 = make_float4(0.f, 0.f, 0.f, 0.f);

    const char* sAhi = sm8 + SM_A_HI;
    const char* sAlo = sm8 + SM_A_LO;
    const char* sRhi = sm8 + SM_R_HI;
    const char* sRlo = sm8 + SM_R_LO;
    float* sP = (float*)(sm8 + SM_R_HI);  // [64][132] partial bounce
    const int pbase = (ks * 16 + mt) * 64;

    for (int t = 0; t < TT; t++) {
        if (t > 0) {
            // stage res tile [64][256] hi/lo
            for (int idx = tid; idx < 2048; idx += NTHR) {
                int row = idx >> 5, kc = idx & 31;
                *(uint4*)(sm8 + SM_R_HI + row * ROWB + kc * 16) =
                    *(const uint4*)&g_reshi[row * RR + ks * 256 + kc * 8];
                *(uint4*)(sm8 + SM_R_LO + row * ROWB + kc * 16) =
                    *(const uint4*)&g_reslo[row * RR + ks * 256 + kc * 8];
            }
            __syncthreads();
            float acc[2][4][4];
#pragma unroll
            for (int mi = 0; mi < 2; mi++)
#pragma unroll
                for (int ni = 0; ni < 4; ni++)
#pragma unroll
                    for (int q = 0; q < 4; q++) acc[mi][ni][q] = 0.f;
#pragma unroll 2
            for (int k16 = 0; k16 < 16; k16++) {
                const int kb = k16 * 32 + 4 * tg;
                unsigned ah[2][4], al[2][4], bh[4][2], bl[4][2];
#pragma unroll
                for (int mi = 0; mi < 2; mi++) {
                    const int rb = (32 * mw + 16 * mi + g) * ROWB;
                    ah[mi][0] = *(const unsigned*)(sAhi + rb + kb);
                    ah[mi][1] = *(const unsigned*)(sAhi + rb + 8 * ROWB + kb);
                    ah[mi][2] = *(const unsigned*)(sAhi + rb + kb + 16);
                    ah[mi][3] =
                        *(const unsigned*)(sAhi + rb + 8 * ROWB + kb + 16);
                    al[mi][0] = *(const unsigned*)(sAlo + rb + kb);
                    al[mi][1] = *(const unsigned*)(sAlo + rb + 8 * ROWB + kb);
                    al[mi][2] = *(const unsigned*)(sAlo + rb + kb + 16);
                    al[mi][3] =
                        *(const unsigned*)(sAlo + rb + 8 * ROWB + kb + 16);
                }
#pragma unroll
                for (int ni = 0; ni < 4; ni++) {
                    const int rb = ((4 * nh + ni) * 8 + g) * ROWB;
                    bh[ni][0] = *(const unsigned*)(sRhi + rb + kb);
                    bh[ni][1] = *(const unsigned*)(sRhi + rb + kb + 16);
                    bl[ni][0] = *(const unsigned*)(sRlo + rb + kb);
                    bl[ni][1] = *(const unsigned*)(sRlo + rb + kb + 16);
                }
                // term-major: 8 independent accs between same-acc touches
#pragma unroll
                for (int mi = 0; mi < 2; mi++)
#pragma unroll
                    for (int ni = 0; ni < 4; ni++)
                        mma_bf16(acc[mi][ni], ah[mi], bh[ni]);
#pragma unroll
                for (int mi = 0; mi < 2; mi++)
#pragma unroll
                    for (int ni = 0; ni < 4; ni++)
                        mma_bf16(acc[mi][ni], ah[mi], bl[ni]);
#pragma unroll
                for (int mi = 0; mi < 2; mi++)
#pragma unroll
                    for (int ni = 0; ni < 4; ni++)
                        mma_bf16(acc[mi][ni], al[mi], bh[ni]);
            }
            __syncthreads();  // res tiles dead; sP overlays SM_R_HI
            // scatter accs into sP[b][jr] (conflict-free banks)
#pragma unroll
            for (int mi = 0; mi < 2; mi++) {
                const int jr = 32 * mw + 16 * mi + g;
#pragma unroll
                for (int ni = 0; ni < 4; ni++) {
                    const int bc = (4 * nh + ni) * 8 + 2 * tg;
                    sP[bc * 132 + jr] = acc[mi][ni][0];
                    sP[(bc + 1) * 132 + jr] = acc[mi][ni][1];
                    sP[bc * 132 + jr + 8] = acc[mi][ni][2];
                    sP[(bc + 1) * 132 + jr + 8] = acc[mi][ni][3];
                }
            }
            __syncthreads();
            // coalesced copy sP -> g_part[(pbase+b)*128 + jr]
            for (int i = tid; i < 2048; i += NTHR) {
                const int b = i >> 5, jq = (i & 31) * 4;
                float4 v = *(const float4*)&sP[b * 132 + jq];
                *(float4*)&g_part[(pbase + b) * 128 + jq] = v;
            }
            grid_sync();
        }
        // ---- epilogue: one float4 (b_e, j0..j0+3) ----
        float4 q = make_float4(0.f, 0.f, 0.f, 0.f);
        if (t > 0) {
#pragma unroll
            for (int s = 0; s < 8; s++) {
                float4 pa = *(const float4*)
                    &g_part[((s * 16 + mt_e) * 64 + b_e) * 128 + jr0];
                q.x += pa.x; q.y += pa.y; q.z += pa.z; q.w += pa.w;
            }
        }
        float4 xv = *(const float4*)&hid[(b_e * TT + t) * RR + j0];
        float4 nr;
        nr.x = 0.5f * p0.x + 0.5f * tanhf(q.x + xv.x);
        nr.y = 0.5f * p0.y + 0.5f * tanhf(q.y + xv.y);
        nr.z = 0.5f * p0.z + 0.5f * tanhf(q.z + xv.z);
        nr.w = 0.5f * p0.w + 0.5f * tanhf(q.w + xv.w);
        p0 = nr;
        *(float4*)&hid[(b_e * TT + t) * RR + j0] = nr;
        float h0 = __bfloat162float(__float2bfloat16_rn(nr.x));
        float h1 = __bfloat162float(__float2bfloat16_rn(nr.y));
        float h2 = __bfloat162float(__float2bfloat16_rn(nr.z));
        float h3 = __bfloat162float(__float2bfloat16_rn(nr.w));
        uint2 uh, ul;
        uh.x = pk(h0, h1);
        uh.y = pk(h2, h3);
        ul.x = pk(nr.x - h0, nr.y - h1);
        ul.y = pk(nr.z - h2, nr.w - h3);
        *(uint2*)&g_reshi[b_e * RR + j0] = uh;
        *(uint2*)&g_reslo[b_e * RR + j0] = ul;
        grid_sync();
    }

    // =========== Readout ===========
    if (cta < BB) {
        const float* res = &hid[(cta * TT + (TT - 1)) * RR];
        float acc[OO];
#pragma unroll
        for (int o = 0; o < OO; o++) acc[o] = 0.f;
        for (int r = tid; r < RR; r += NTHR) {
            float rv = res[r];
#pragma unroll
            for (int o = 0; o < OO; o++) acc[o] += rv * ow[r * OO + o];
        }
        float* red = (float*)sm8;
        __syncthreads();
#pragma unroll
        for (int o = 0; o < OO; o++) red[o * NTHR + tid] = acc[o];
        __syncthreads();
        for (int s2 = NTHR / 2; s2 > 0; s2 >>= 1) {
            if (tid < s2) {
#pragma unroll
                for (int o = 0; o < OO; o++)
                    red[o * NTHR + tid] += red[o * NTHR + tid + s2];
            }
            __syncthreads();
        }
        if (tid < OO) out[cta * OO + tid] = red[tid * NTHR] + ob[tid];
    }
}

extern "C" void kernel_launch(void* const* d_in, const int* in_sizes, int n_in,
                              void* d_out, int out_size) {
    const float* x = (const float*)d_in[0];
    const float* i2h = (const float*)d_in[1];
    const float* h2h = (const float*)d_in[2];
    const float* ow = (const float*)d_in[3];
    const float* ob = (const float*)d_in[4];
    float* out = (float*)d_out;
    float* hid = out + BB * OO;

    cudaFuncSetAttribute(esn_mma, cudaFuncAttributeMaxDynamicSharedMemorySize,
                         SM_TOTAL);
    esn_mma<<<NCTA, NTHR, SM_TOTAL>>>(x, i2h, h2h, ow, ob, out, hid);
}